// round 1
// baseline (speedup 1.0000x reference)
#include <cuda_runtime.h>
#include <math.h>

#define EPSQ 1e-5f
#define QBF  127.0f

#define S_LEN 2048
#define D_DIM 2048
#define P_DIM 16
#define HEADS 16
#define HD    128
#define BATCH 2
#define NTOK  (BATCH * S_LEN)
#define BHTOT (BATCH * HEADS)

// ---------------- scratch (no allocations allowed) ----------------
__device__ float g_proj[3][(size_t)BHTOT * S_LEN * HD];   // q,k,v in [bh][s][hd]
__device__ int4  g_wq[6][2048];                            // ternary int8 weights, 32 KB each
__device__ float g_wscale[6];                              // clip(mean|w|, eps)

// ---------------- weight quantization ----------------
__global__ void quant_weights_kernel(const float* __restrict__ w0, const float* __restrict__ w1,
                                     const float* __restrict__ w2, const float* __restrict__ w3,
                                     const float* __restrict__ w4, const float* __restrict__ w5) {
    const float* ws[6] = {w0, w1, w2, w3, w4, w5};
    const int j = blockIdx.x;
    const float* w = ws[j];
    const int N = P_DIM * D_DIM;   // 32768 for both layouts
    int tid = threadIdx.x;

    float sum = 0.f;
    for (int i = tid; i < N; i += 256) sum += fabsf(w[i]);
    #pragma unroll
    for (int o = 16; o > 0; o >>= 1) sum += __shfl_xor_sync(0xffffffffu, sum, o);
    __shared__ float red[8];
    __shared__ float s_invws;
    if ((tid & 31) == 0) red[tid >> 5] = sum;
    __syncthreads();
    if (tid == 0) {
        float t = 0.f;
        for (int k = 0; k < 8; k++) t += red[k];
        float mean = t / (float)N;
        float sc = fmaxf(mean, EPSQ);   // clip(mean|w|, eps)
        g_wscale[j] = sc;
        s_invws = 1.0f / sc;            // ws
    }
    __syncthreads();
    float wsv = s_invws;
    char* out = (char*)g_wq[j];
    for (int i = tid; i < N; i += 256) {
        float q = rintf(w[i] * wsv);            // round half-to-even like jnp.round
        q = fminf(fmaxf(q, -1.f), 1.f);
        out[i] = (char)(int)q;
    }
}

// ---------------- fused projection: bitlinear -> gelu -> l2norm -> bitlinear ----------------
__global__ __launch_bounds__(256) void proj_kernel(const float* __restrict__ x) {
    const int t = blockIdx.x;           // token index
    const int b = t >> 11;
    const int s = t & 2047;
    const int tid = threadIdx.x;

    __shared__ float xs[D_DIM];
    __shared__ int   xq[D_DIM / 4];     // packed int8
    __shared__ float redf[8 * 16];
    __shared__ float rmax[8];
    __shared__ float s_cmax;
    __shared__ int   aqp[3][4];         // packed quantized activations (16 int8 per m)
    __shared__ float fct[3];            // dequant factor for second bitlinear

    // -------- load x row, compute absmax --------
    const float* xr = x + (size_t)t * D_DIM;
    float mx = 0.f;
    for (int i = tid; i < D_DIM / 4; i += 256) {
        float4 v = ((const float4*)xr)[i];
        ((float4*)xs)[i] = v;
        mx = fmaxf(mx, fmaxf(fmaxf(fabsf(v.x), fabsf(v.y)), fmaxf(fabsf(v.z), fabsf(v.w))));
    }
    #pragma unroll
    for (int o = 16; o > 0; o >>= 1) mx = fmaxf(mx, __shfl_xor_sync(0xffffffffu, mx, o));
    if ((tid & 31) == 0) rmax[tid >> 5] = mx;
    __syncthreads();
    if (tid == 0) {
        float m = rmax[0];
        for (int k = 1; k < 8; k++) m = fmaxf(m, rmax[k]);
        s_cmax = fmaxf(m, EPSQ);
    }
    __syncthreads();
    const float cmax = s_cmax;
    const float sx = QBF / cmax;

    // -------- quantize x row (pack int8 x4 into int) --------
    {
        int base = tid * 8;
        #pragma unroll
        for (int g = 0; g < 2; g++) {
            int v = 0;
            #pragma unroll
            for (int u = 0; u < 4; u++) {
                float q = rintf(xs[base + g * 4 + u] * sx);
                q = fminf(fmaxf(q, -128.f), 127.f);
                v |= (((int)q) & 0xFF) << (8 * u);
            }
            xq[tid * 2 + g] = v;
        }
    }
    __syncthreads();

    const int x0 = xq[tid * 2 + 0];
    const int x1 = xq[tid * 2 + 1];

    // -------- phase A: first bitlinear + gelu + l2norm + quantize a, for m in {q,k,v} --------
    for (int m = 0; m < 3; m++) {
        const int* wmat = (const int*)g_wq[2 * m];   // [16][512] packed ints
        int acc[16];
        #pragma unroll
        for (int p = 0; p < 16; p++) {
            const int* wp = wmat + p * 512;
            int a = __dp4a(x0, wp[tid * 2 + 0], 0);
            a = __dp4a(x1, wp[tid * 2 + 1], a);
            acc[p] = a;
        }
        #pragma unroll
        for (int p = 0; p < 16; p++)
            #pragma unroll
            for (int o = 16; o > 0; o >>= 1) acc[p] += __shfl_xor_sync(0xffffffffu, acc[p], o);
        if ((tid & 31) == 0) {
            #pragma unroll
            for (int p = 0; p < 16; p++) redf[(tid >> 5) * 16 + p] = (float)acc[p];
        }
        __syncthreads();
        if (tid < 16) {
            float tot = 0.f;
            #pragma unroll
            for (int w = 0; w < 8; w++) tot += redf[w * 16 + tid];
            float a = tot * (cmax / QBF) * g_wscale[2 * m];
            // exact GELU
            float h = 0.5f * a * (1.0f + erff(a * 0.70710678118654752f));
            // L2 normalize over 16, * sqrt(16)
            float ss = h * h;
            #pragma unroll
            for (int o = 8; o > 0; o >>= 1) ss += __shfl_xor_sync(0x0000ffffu, ss, o, 16);
            float nrm = fmaxf(sqrtf(ss), 1e-12f);
            h = h / nrm * 4.0f;
            // quantize a
            float am = fabsf(h);
            #pragma unroll
            for (int o = 8; o > 0; o >>= 1) am = fmaxf(am, __shfl_xor_sync(0x0000ffffu, am, o, 16));
            am = fmaxf(am, EPSQ);
            float sa = QBF / am;
            float q = fminf(fmaxf(rintf(h * sa), -128.f), 127.f);
            ((char*)&aqp[m][0])[tid] = (char)(int)q;
            if (tid == 0) fct[m] = (am / QBF) * g_wscale[2 * m + 1];
        }
        __syncthreads();
    }

    // -------- phase B: second bitlinear, write to [bh][s][hd] --------
    #pragma unroll
    for (int j = 0; j < 8; j++) {
        int d = tid + 256 * j;
        int h = d >> 7, dh = d & 127;
        size_t oidx = ((size_t)(b * HEADS + h) * S_LEN + s) * HD + dh;
        #pragma unroll
        for (int m = 0; m < 3; m++) {
            const int4 wv = g_wq[2 * m + 1][d];   // 16 int8 of row d
            int acc = __dp4a(aqp[m][0], wv.x, 0);
            acc = __dp4a(aqp[m][1], wv.y, acc);
            acc = __dp4a(aqp[m][2], wv.z, acc);
            acc = __dp4a(aqp[m][3], wv.w, acc);
            g_proj[m][oidx] = (float)acc * fct[m];
        }
    }
}

// ---------------- flash attention (fp32, 64x64 tiles) ----------------
#define LDA 132   // row stride (floats) for Q/K/V tiles
#define LDP 65    // row stride for P tile
#define ATTN_SMEM ((3 * 64 * LDA + 64 * LDP) * 4)

__global__ __launch_bounds__(256) void attn_kernel(float* __restrict__ out) {
    extern __shared__ float sm[];
    float* Qs = sm;
    float* Ks = Qs + 64 * LDA;
    float* Vs = Ks + 64 * LDA;
    float* Ps = Vs + 64 * LDA;

    const int bh = blockIdx.y;
    const int q0 = blockIdx.x * 64;
    const int tid = threadIdx.x;
    const int tx = tid & 15;
    const int ty = tid >> 4;

    const float* gq = g_proj[0];
    const float* gk = g_proj[1];
    const float* gv = g_proj[2];

    // load Q tile
    const float* qbase = gq + ((size_t)bh * S_LEN + q0) * HD;
    for (int i = tid; i < 64 * 32; i += 256) {
        int r = i >> 5, c4 = i & 31;
        ((float4*)(Qs + r * LDA))[c4] = ((const float4*)(qbase + r * HD))[c4];
    }

    float m_i[4], l_i[4];
    float o[4][8];
    #pragma unroll
    for (int r = 0; r < 4; r++) {
        m_i[r] = -INFINITY; l_i[r] = 0.f;
        #pragma unroll
        for (int c = 0; c < 8; c++) o[r][c] = 0.f;
    }

    const float scale = 0.08838834764831845f;  // 1/sqrt(128)

    for (int j = 0; j < S_LEN; j += 64) {
        const float* kb = gk + ((size_t)bh * S_LEN + j) * HD;
        const float* vb = gv + ((size_t)bh * S_LEN + j) * HD;
        for (int i = tid; i < 64 * 32; i += 256) {
            int r = i >> 5, c4 = i & 31;
            ((float4*)(Ks + r * LDA))[c4] = ((const float4*)(kb + r * HD))[c4];
            ((float4*)(Vs + r * LDA))[c4] = ((const float4*)(vb + r * HD))[c4];
        }
        __syncthreads();

        // S = Q K^T  (thread covers rows 4ty+r, key cols tx+16c)
        float sv[4][4];
        #pragma unroll
        for (int r = 0; r < 4; r++)
            #pragma unroll
            for (int c = 0; c < 4; c++) sv[r][c] = 0.f;

        #pragma unroll 4
        for (int k4 = 0; k4 < 32; k4++) {
            float4 qv[4], kv[4];
            #pragma unroll
            for (int r = 0; r < 4; r++) qv[r] = ((const float4*)(Qs + (4 * ty + r) * LDA))[k4];
            #pragma unroll
            for (int c = 0; c < 4; c++) kv[c] = ((const float4*)(Ks + (tx + 16 * c) * LDA))[k4];
            #pragma unroll
            for (int r = 0; r < 4; r++)
                #pragma unroll
                for (int c = 0; c < 4; c++) {
                    sv[r][c] += qv[r].x * kv[c].x;
                    sv[r][c] += qv[r].y * kv[c].y;
                    sv[r][c] += qv[r].z * kv[c].z;
                    sv[r][c] += qv[r].w * kv[c].w;
                }
        }

        // online softmax per row band
        #pragma unroll
        for (int r = 0; r < 4; r++) {
            float mt = -INFINITY;
            #pragma unroll
            for (int c = 0; c < 4; c++) { sv[r][c] *= scale; mt = fmaxf(mt, sv[r][c]); }
            #pragma unroll
            for (int ofs = 8; ofs > 0; ofs >>= 1) mt = fmaxf(mt, __shfl_xor_sync(0xffffffffu, mt, ofs, 16));
            float mnew = fmaxf(m_i[r], mt);
            float corr = __expf(m_i[r] - mnew);
            m_i[r] = mnew;
            float rs = 0.f;
            #pragma unroll
            for (int c = 0; c < 4; c++) {
                float p = __expf(sv[r][c] - mnew);
                sv[r][c] = p;
                rs += p;
            }
            #pragma unroll
            for (int ofs = 8; ofs > 0; ofs >>= 1) rs += __shfl_xor_sync(0xffffffffu, rs, ofs, 16);
            l_i[r] = l_i[r] * corr + rs;
            #pragma unroll
            for (int c = 0; c < 8; c++) o[r][c] *= corr;
            #pragma unroll
            for (int c = 0; c < 4; c++) Ps[(4 * ty + r) * LDP + tx + 16 * c] = sv[r][c];
        }
        __syncthreads();

        // O += P @ V   (thread covers rows 4ty+r, cols {4tx..4tx+3} and {64+4tx..})
        #pragma unroll 2
        for (int jj = 0; jj < 64; jj++) {
            float4 v0 = ((const float4*)(Vs + jj * LDA))[tx];
            float4 v1 = ((const float4*)(Vs + jj * LDA))[16 + tx];
            #pragma unroll
            for (int r = 0; r < 4; r++) {
                float p = Ps[(4 * ty + r) * LDP + jj];
                o[r][0] += p * v0.x; o[r][1] += p * v0.y;
                o[r][2] += p * v0.z; o[r][3] += p * v0.w;
                o[r][4] += p * v1.x; o[r][5] += p * v1.y;
                o[r][6] += p * v1.z; o[r][7] += p * v1.w;
            }
        }
        __syncthreads();
    }

    // epilogue: normalize and store to [B,S,D]
    const int b = bh >> 4, h = bh & 15;
    #pragma unroll
    for (int r = 0; r < 4; r++) {
        int srow = q0 + 4 * ty + r;
        float inv = 1.0f / l_i[r];
        float* op = out + ((size_t)(b * S_LEN + srow)) * D_DIM + h * HD;
        float4 a = make_float4(o[r][0] * inv, o[r][1] * inv, o[r][2] * inv, o[r][3] * inv);
        float4 bq = make_float4(o[r][4] * inv, o[r][5] * inv, o[r][6] * inv, o[r][7] * inv);
        ((float4*)op)[tx] = a;
        ((float4*)op)[16 + tx] = bq;
    }
}

// ---------------- launch ----------------
extern "C" void kernel_launch(void* const* d_in, const int* in_sizes, int n_in,
                              void* d_out, int out_size) {
    const float* x = (const float*)d_in[0];

    quant_weights_kernel<<<6, 256>>>((const float*)d_in[1], (const float*)d_in[2],
                                     (const float*)d_in[3], (const float*)d_in[4],
                                     (const float*)d_in[5], (const float*)d_in[6]);

    proj_kernel<<<NTOK, 256>>>(x);

    static bool attr_set = false;
    if (!attr_set) {
        cudaFuncSetAttribute(attn_kernel, cudaFuncAttributeMaxDynamicSharedMemorySize, ATTN_SMEM);
        attr_set = true;
    }
    attn_kernel<<<dim3(S_LEN / 64, BHTOT), 256, ATTN_SMEM>>>((float*)d_out);
}

// round 2
// speedup vs baseline: 3.0958x; 3.0958x over previous
#include <cuda_runtime.h>
#include <math.h>
#include <stdint.h>

#define EPSQ 1e-5f
#define QBF  127.0f

#define S_LEN 2048
#define D_DIM 2048
#define P_DIM 16
#define HEADS 16
#define HD    128
#define BATCH 2
#define NTOK  (BATCH * S_LEN)
#define BHTOT (BATCH * HEADS)

// ---------------- scratch (no allocations allowed) ----------------
__device__ float g_proj[3][(size_t)BHTOT * S_LEN * HD];   // q,k,v in [bh][s][hd]
__device__ int4  g_wq[6][2048];                            // ternary int8 weights
__device__ float g_wscale[6];

// ---------------- weight quantization ----------------
__global__ void quant_weights_kernel(const float* __restrict__ w0, const float* __restrict__ w1,
                                     const float* __restrict__ w2, const float* __restrict__ w3,
                                     const float* __restrict__ w4, const float* __restrict__ w5) {
    const float* ws[6] = {w0, w1, w2, w3, w4, w5};
    const int j = blockIdx.x;
    const float* w = ws[j];
    const int N = P_DIM * D_DIM;
    int tid = threadIdx.x;

    float sum = 0.f;
    for (int i = tid; i < N; i += 256) sum += fabsf(w[i]);
    #pragma unroll
    for (int o = 16; o > 0; o >>= 1) sum += __shfl_xor_sync(0xffffffffu, sum, o);
    __shared__ float red[8];
    __shared__ float s_invws;
    if ((tid & 31) == 0) red[tid >> 5] = sum;
    __syncthreads();
    if (tid == 0) {
        float t = 0.f;
        for (int k = 0; k < 8; k++) t += red[k];
        float mean = t / (float)N;
        float sc = fmaxf(mean, EPSQ);
        g_wscale[j] = sc;
        s_invws = 1.0f / sc;
    }
    __syncthreads();
    float wsv = s_invws;
    char* out = (char*)g_wq[j];
    for (int i = tid; i < N; i += 256) {
        float q = rintf(w[i] * wsv);
        q = fminf(fmaxf(q, -1.f), 1.f);
        out[i] = (char)(int)q;
    }
}

// ---------------- fused projection ----------------
__global__ __launch_bounds__(256) void proj_kernel(const float* __restrict__ x) {
    const int t = blockIdx.x;
    const int b = t >> 11;
    const int s = t & 2047;
    const int tid = threadIdx.x;

    __shared__ float xs[D_DIM];
    __shared__ int   xq[D_DIM / 4];
    __shared__ float redf[8 * 16];
    __shared__ float rmax[8];
    __shared__ float s_cmax;
    __shared__ int   aqp[3][4];
    __shared__ float fct[3];

    const float* xr = x + (size_t)t * D_DIM;
    float mx = 0.f;
    for (int i = tid; i < D_DIM / 4; i += 256) {
        float4 v = ((const float4*)xr)[i];
        ((float4*)xs)[i] = v;
        mx = fmaxf(mx, fmaxf(fmaxf(fabsf(v.x), fabsf(v.y)), fmaxf(fabsf(v.z), fabsf(v.w))));
    }
    #pragma unroll
    for (int o = 16; o > 0; o >>= 1) mx = fmaxf(mx, __shfl_xor_sync(0xffffffffu, mx, o));
    if ((tid & 31) == 0) rmax[tid >> 5] = mx;
    __syncthreads();
    if (tid == 0) {
        float m = rmax[0];
        for (int k = 1; k < 8; k++) m = fmaxf(m, rmax[k]);
        s_cmax = fmaxf(m, EPSQ);
    }
    __syncthreads();
    const float cmax = s_cmax;
    const float sx = QBF / cmax;

    {
        int base = tid * 8;
        #pragma unroll
        for (int g = 0; g < 2; g++) {
            int v = 0;
            #pragma unroll
            for (int u = 0; u < 4; u++) {
                float q = rintf(xs[base + g * 4 + u] * sx);
                q = fminf(fmaxf(q, -128.f), 127.f);
                v |= (((int)q) & 0xFF) << (8 * u);
            }
            xq[tid * 2 + g] = v;
        }
    }
    __syncthreads();

    const int x0 = xq[tid * 2 + 0];
    const int x1 = xq[tid * 2 + 1];

    for (int m = 0; m < 3; m++) {
        const int* wmat = (const int*)g_wq[2 * m];
        int acc[16];
        #pragma unroll
        for (int p = 0; p < 16; p++) {
            const int* wp = wmat + p * 512;
            int a = __dp4a(x0, wp[tid * 2 + 0], 0);
            a = __dp4a(x1, wp[tid * 2 + 1], a);
            acc[p] = a;
        }
        #pragma unroll
        for (int p = 0; p < 16; p++)
            #pragma unroll
            for (int o = 16; o > 0; o >>= 1) acc[p] += __shfl_xor_sync(0xffffffffu, acc[p], o);
        if ((tid & 31) == 0) {
            #pragma unroll
            for (int p = 0; p < 16; p++) redf[(tid >> 5) * 16 + p] = (float)acc[p];
        }
        __syncthreads();
        if (tid < 16) {
            float tot = 0.f;
            #pragma unroll
            for (int w = 0; w < 8; w++) tot += redf[w * 16 + tid];
            float a = tot * (cmax / QBF) * g_wscale[2 * m];
            float h = 0.5f * a * (1.0f + erff(a * 0.70710678118654752f));
            float ss = h * h;
            #pragma unroll
            for (int o = 8; o > 0; o >>= 1) ss += __shfl_xor_sync(0x0000ffffu, ss, o, 16);
            float nrm = fmaxf(sqrtf(ss), 1e-12f);
            h = h / nrm * 4.0f;
            float am = fabsf(h);
            #pragma unroll
            for (int o = 8; o > 0; o >>= 1) am = fmaxf(am, __shfl_xor_sync(0x0000ffffu, am, o, 16));
            am = fmaxf(am, EPSQ);
            float sa = QBF / am;
            float q = fminf(fmaxf(rintf(h * sa), -128.f), 127.f);
            ((char*)&aqp[m][0])[tid] = (char)(int)q;
            if (tid == 0) fct[m] = (am / QBF) * g_wscale[2 * m + 1];
        }
        __syncthreads();
    }

    #pragma unroll
    for (int j = 0; j < 8; j++) {
        int d = tid + 256 * j;
        int h = d >> 7, dh = d & 127;
        size_t oidx = ((size_t)(b * HEADS + h) * S_LEN + s) * HD + dh;
        #pragma unroll
        for (int m = 0; m < 3; m++) {
            const int4 wv = g_wq[2 * m + 1][d];
            int acc = __dp4a(aqp[m][0], wv.x, 0);
            acc = __dp4a(aqp[m][1], wv.y, acc);
            acc = __dp4a(aqp[m][2], wv.z, acc);
            acc = __dp4a(aqp[m][3], wv.w, acc);
            g_proj[m][oidx] = (float)acc * fct[m];
        }
    }
}

// ---------------- flash attention: tf32 tensor-core mma ----------------
#define BM 128
#define BN 64
#define QLD 132
#define KLD 132
#define VLD 136
#define ATTN_SMEM_BYTES ((64 * KLD + 64 * VLD) * 4)   // 68608 (>= Q stage 128*132*4)

__device__ __forceinline__ uint32_t f2tf(float f) {
    uint32_t u;
    asm("cvt.rna.tf32.f32 %0, %1;" : "=r"(u) : "f"(f));
    return u;
}

__device__ __forceinline__ void mma_tf32(float* d, const uint32_t* a, const uint32_t* b) {
    asm volatile("mma.sync.aligned.m16n8k8.row.col.f32.tf32.tf32.f32 "
        "{%0,%1,%2,%3}, {%4,%5,%6,%7}, {%8,%9}, {%0,%1,%2,%3};"
        : "+f"(d[0]), "+f"(d[1]), "+f"(d[2]), "+f"(d[3])
        : "r"(a[0]), "r"(a[1]), "r"(a[2]), "r"(a[3]), "r"(b[0]), "r"(b[1]));
}

__global__ __launch_bounds__(256, 1) void attn_kernel(float* __restrict__ out) {
    extern __shared__ float sm[];
    float* Ks = sm;                 // [64][KLD]
    float* Vs = sm + 64 * KLD;      // [64][VLD]

    const int bh = blockIdx.y;
    const int q0 = blockIdx.x * BM;
    const int tid = threadIdx.x;
    const int w = tid >> 5;
    const int lane = tid & 31;
    const int g = lane >> 2;       // group (row within m-tile)
    const int t = lane & 3;        // thread-in-group

    const float scale = 0.08838834764831845f;  // 1/sqrt(128)

    // -------- stage Q (scaled + tf32) into smem, then into A-fragments --------
    const float* qb = g_proj[0] + ((size_t)bh * S_LEN + q0) * HD;
    for (int i = tid; i < 128 * 32; i += 256) {
        int r = i >> 5, c = i & 31;
        float4 v = ((const float4*)(qb + (size_t)r * HD))[c];
        uint4 u;
        u.x = f2tf(v.x * scale); u.y = f2tf(v.y * scale);
        u.z = f2tf(v.z * scale); u.w = f2tf(v.w * scale);
        ((uint4*)(sm + r * QLD))[c] = u;
    }
    __syncthreads();

    uint32_t qa[16][4];
    {
        const uint32_t* Q = (const uint32_t*)sm;
        const int r0 = (16 * w + g) * QLD;
        const int r1 = r0 + 8 * QLD;
        #pragma unroll
        for (int kk = 0; kk < 16; kk++) {
            int c = kk * 8 + t;
            qa[kk][0] = Q[r0 + c];
            qa[kk][1] = Q[r1 + c];
            qa[kk][2] = Q[r0 + c + 4];
            qa[kk][3] = Q[r1 + c + 4];
        }
    }
    __syncthreads();

    float o[16][4];
    #pragma unroll
    for (int nt = 0; nt < 16; nt++) {
        o[nt][0] = 0.f; o[nt][1] = 0.f; o[nt][2] = 0.f; o[nt][3] = 0.f;
    }
    float m0 = -INFINITY, m1 = -INFINITY, l0 = 0.f, l1 = 0.f;

    const float* kbase = g_proj[1] + (size_t)bh * S_LEN * HD;
    const float* vbase = g_proj[2] + (size_t)bh * S_LEN * HD;

    for (int j = 0; j < S_LEN; j += BN) {
        // -------- copy K,V tile (tf32-converted) --------
        for (int i = tid; i < 64 * 32; i += 256) {
            int r = i >> 5, c = i & 31;
            float4 kv = ((const float4*)(kbase + (size_t)(j + r) * HD))[c];
            float4 vv = ((const float4*)(vbase + (size_t)(j + r) * HD))[c];
            uint4 ku, vu;
            ku.x = f2tf(kv.x); ku.y = f2tf(kv.y); ku.z = f2tf(kv.z); ku.w = f2tf(kv.w);
            vu.x = f2tf(vv.x); vu.y = f2tf(vv.y); vu.z = f2tf(vv.z); vu.w = f2tf(vv.w);
            ((uint4*)(Ks + r * KLD))[c] = ku;
            ((uint4*)(Vs + r * VLD))[c] = vu;
        }
        __syncthreads();

        // -------- S = (Q*scale) K^T  via mma --------
        float s[8][4];
        #pragma unroll
        for (int nt = 0; nt < 8; nt++) {
            s[nt][0] = 0.f; s[nt][1] = 0.f; s[nt][2] = 0.f; s[nt][3] = 0.f;
        }
        const uint32_t* KU = (const uint32_t*)Ks;
        #pragma unroll
        for (int kk = 0; kk < 16; kk++) {
            #pragma unroll
            for (int nt = 0; nt < 8; nt++) {
                uint32_t b[2];
                int idx = (nt * 8 + g) * KLD + kk * 8 + t;
                b[0] = KU[idx];
                b[1] = KU[idx + 4];
                mma_tf32(s[nt], qa[kk], b);
            }
        }

        // -------- online softmax (rows: r0 = g, r1 = g+8 within warp band) --------
        float mt0 = -INFINITY, mt1 = -INFINITY;
        #pragma unroll
        for (int nt = 0; nt < 8; nt++) {
            mt0 = fmaxf(mt0, fmaxf(s[nt][0], s[nt][1]));
            mt1 = fmaxf(mt1, fmaxf(s[nt][2], s[nt][3]));
        }
        mt0 = fmaxf(mt0, __shfl_xor_sync(0xffffffffu, mt0, 1));
        mt0 = fmaxf(mt0, __shfl_xor_sync(0xffffffffu, mt0, 2));
        mt1 = fmaxf(mt1, __shfl_xor_sync(0xffffffffu, mt1, 1));
        mt1 = fmaxf(mt1, __shfl_xor_sync(0xffffffffu, mt1, 2));

        float mn0 = fmaxf(m0, mt0), mn1 = fmaxf(m1, mt1);
        float c0 = __expf(m0 - mn0), c1 = __expf(m1 - mn1);
        m0 = mn0; m1 = mn1;

        float rs0 = 0.f, rs1 = 0.f;
        #pragma unroll
        for (int nt = 0; nt < 8; nt++) {
            s[nt][0] = __expf(s[nt][0] - mn0);
            s[nt][1] = __expf(s[nt][1] - mn0);
            s[nt][2] = __expf(s[nt][2] - mn1);
            s[nt][3] = __expf(s[nt][3] - mn1);
            rs0 += s[nt][0] + s[nt][1];
            rs1 += s[nt][2] + s[nt][3];
        }
        rs0 += __shfl_xor_sync(0xffffffffu, rs0, 1);
        rs0 += __shfl_xor_sync(0xffffffffu, rs0, 2);
        rs1 += __shfl_xor_sync(0xffffffffu, rs1, 1);
        rs1 += __shfl_xor_sync(0xffffffffu, rs1, 2);
        l0 = l0 * c0 + rs0;
        l1 = l1 * c1 + rs1;

        #pragma unroll
        for (int nt = 0; nt < 16; nt++) {
            o[nt][0] *= c0; o[nt][1] *= c0;
            o[nt][2] *= c1; o[nt][3] *= c1;
        }

        // -------- O += P @ V  (P frags built from S frags via quad shuffles) --------
        const uint32_t* VU = (const uint32_t*)Vs;
        #pragma unroll
        for (int kk = 0; kk < 8; kk++) {
            uint32_t u0 = f2tf(s[kk][0]), u1 = f2tf(s[kk][1]);
            uint32_t u2 = f2tf(s[kk][2]), u3 = f2tf(s[kk][3]);
            int srcA = t >> 1;
            int srcB = srcA + 2;
            uint32_t x0 = __shfl_sync(0xffffffffu, u0, srcA, 4);
            uint32_t x1 = __shfl_sync(0xffffffffu, u1, srcA, 4);
            uint32_t y0 = __shfl_sync(0xffffffffu, u0, srcB, 4);
            uint32_t y1 = __shfl_sync(0xffffffffu, u1, srcB, 4);
            uint32_t z0 = __shfl_sync(0xffffffffu, u2, srcA, 4);
            uint32_t z1 = __shfl_sync(0xffffffffu, u3, srcA, 4);
            uint32_t v0 = __shfl_sync(0xffffffffu, u2, srcB, 4);
            uint32_t v1 = __shfl_sync(0xffffffffu, u3, srcB, 4);
            uint32_t pa[4];
            pa[0] = (t & 1) ? x1 : x0;   // (row g,   col t)
            pa[1] = (t & 1) ? z1 : z0;   // (row g+8, col t)
            pa[2] = (t & 1) ? y1 : y0;   // (row g,   col t+4)
            pa[3] = (t & 1) ? v1 : v0;   // (row g+8, col t+4)

            #pragma unroll
            for (int nt = 0; nt < 16; nt++) {
                uint32_t b[2];
                int idx = (kk * 8 + t) * VLD + nt * 8 + g;
                b[0] = VU[idx];
                b[1] = VU[idx + 4 * VLD];
                mma_tf32(o[nt], pa, b);
            }
        }
        __syncthreads();
    }

    // -------- epilogue: normalize, write [B,S,D] --------
    const int b_ = bh >> 4, h = bh & 15;
    const int row0 = q0 + 16 * w + g;
    const int row1 = row0 + 8;
    const float inv0 = 1.0f / l0;
    const float inv1 = 1.0f / l1;
    float* op0 = out + ((size_t)(b_ * S_LEN + row0)) * D_DIM + h * HD;
    float* op1 = out + ((size_t)(b_ * S_LEN + row1)) * D_DIM + h * HD;
    #pragma unroll
    for (int nt = 0; nt < 16; nt++) {
        int c = nt * 8 + 2 * t;
        *(float2*)(op0 + c) = make_float2(o[nt][0] * inv0, o[nt][1] * inv0);
        *(float2*)(op1 + c) = make_float2(o[nt][2] * inv1, o[nt][3] * inv1);
    }
}

// ---------------- launch ----------------
extern "C" void kernel_launch(void* const* d_in, const int* in_sizes, int n_in,
                              void* d_out, int out_size) {
    const float* x = (const float*)d_in[0];

    quant_weights_kernel<<<6, 256>>>((const float*)d_in[1], (const float*)d_in[2],
                                     (const float*)d_in[3], (const float*)d_in[4],
                                     (const float*)d_in[5], (const float*)d_in[6]);

    proj_kernel<<<NTOK, 256>>>(x);

    cudaFuncSetAttribute(attn_kernel, cudaFuncAttributeMaxDynamicSharedMemorySize, ATTN_SMEM_BYTES);
    attn_kernel<<<dim3(S_LEN / BM, BHTOT), 256, ATTN_SMEM_BYTES>>>((float*)d_out);
}

// round 3
// speedup vs baseline: 6.3881x; 2.0635x over previous
#include <cuda_runtime.h>
#include <cuda_bf16.h>
#include <math.h>
#include <stdint.h>

#define EPSQ 1e-5f
#define QBF  127.0f

#define S_LEN 2048
#define D_DIM 2048
#define P_DIM 16
#define HEADS 16
#define HD    128
#define BATCH 2
#define NTOK  (BATCH * S_LEN)
#define BHTOT (BATCH * HEADS)

// ---------------- scratch ----------------
__device__ __nv_bfloat16 g_proj[3][(size_t)BHTOT * S_LEN * HD];   // q(,scaled),k,v  [bh][s][hd]
__device__ __nv_bfloat16 g_vt[(size_t)BHTOT * HD * S_LEN];        // v transposed [bh][hd][s]
__device__ int4  g_wq[6][2048];
__device__ float g_wscale[6];

// ---------------- weight quantization ----------------
__global__ __launch_bounds__(1024) void quant_weights_kernel(
        const float* __restrict__ w0, const float* __restrict__ w1,
        const float* __restrict__ w2, const float* __restrict__ w3,
        const float* __restrict__ w4, const float* __restrict__ w5) {
    const float* ws[6] = {w0, w1, w2, w3, w4, w5};
    const int j = blockIdx.x;
    const float* w = ws[j];
    const int N = P_DIM * D_DIM;
    int tid = threadIdx.x;

    float sum = 0.f;
    for (int i = tid; i < N; i += 1024) sum += fabsf(w[i]);
    #pragma unroll
    for (int o = 16; o > 0; o >>= 1) sum += __shfl_xor_sync(0xffffffffu, sum, o);
    __shared__ float red[32];
    __shared__ float s_invws;
    if ((tid & 31) == 0) red[tid >> 5] = sum;
    __syncthreads();
    if (tid == 0) {
        float t = 0.f;
        for (int k = 0; k < 32; k++) t += red[k];
        float mean = t / (float)N;
        float sc = fmaxf(mean, EPSQ);
        g_wscale[j] = sc;
        s_invws = 1.0f / sc;
    }
    __syncthreads();
    float wsv = s_invws;
    char* out = (char*)g_wq[j];
    for (int i = tid; i < N; i += 1024) {
        float q = rintf(w[i] * wsv);
        q = fminf(fmaxf(q, -1.f), 1.f);
        out[i] = (char)(int)q;
    }
}

// ---------------- fused projection (one block per (token, m)) ----------------
__global__ __launch_bounds__(256) void proj_kernel(const float* __restrict__ x) {
    const int t = blockIdx.x;
    const int m = blockIdx.y;
    const int b = t >> 11;
    const int s = t & 2047;
    const int tid = threadIdx.x;

    __shared__ float xs[D_DIM];
    __shared__ int   xq[D_DIM / 4];
    __shared__ int   redi[8 * 16];
    __shared__ float rmax[8];
    __shared__ float s_cmax;
    __shared__ int   aqp[4];
    __shared__ float fct;

    const float* xr = x + (size_t)t * D_DIM;
    float mx = 0.f;
    for (int i = tid; i < D_DIM / 4; i += 256) {
        float4 v = ((const float4*)xr)[i];
        ((float4*)xs)[i] = v;
        mx = fmaxf(mx, fmaxf(fmaxf(fabsf(v.x), fabsf(v.y)), fmaxf(fabsf(v.z), fabsf(v.w))));
    }
    #pragma unroll
    for (int o = 16; o > 0; o >>= 1) mx = fmaxf(mx, __shfl_xor_sync(0xffffffffu, mx, o));
    if ((tid & 31) == 0) rmax[tid >> 5] = mx;
    __syncthreads();
    if (tid == 0) {
        float mm = rmax[0];
        for (int k = 1; k < 8; k++) mm = fmaxf(mm, rmax[k]);
        s_cmax = fmaxf(mm, EPSQ);
    }
    __syncthreads();
    const float cmax = s_cmax;
    const float sx = QBF / cmax;

    {
        int base = tid * 8;
        #pragma unroll
        for (int g = 0; g < 2; g++) {
            int v = 0;
            #pragma unroll
            for (int u = 0; u < 4; u++) {
                float q = rintf(xs[base + g * 4 + u] * sx);
                q = fminf(fmaxf(q, -128.f), 127.f);
                v |= (((int)q) & 0xFF) << (8 * u);
            }
            xq[tid * 2 + g] = v;
        }
    }
    __syncthreads();

    const int x0 = xq[tid * 2 + 0];
    const int x1 = xq[tid * 2 + 1];

    // phase A: bitlinear -> gelu -> l2norm -> quantize activation
    {
        const int* wmat = (const int*)g_wq[2 * m];
        int acc[16];
        #pragma unroll
        for (int p = 0; p < 16; p++) {
            const int* wp = wmat + p * 512;
            int a = __dp4a(x0, wp[tid * 2 + 0], 0);
            a = __dp4a(x1, wp[tid * 2 + 1], a);
            acc[p] = a;
        }
        #pragma unroll
        for (int p = 0; p < 16; p++) acc[p] = __reduce_add_sync(0xffffffffu, acc[p]);
        if ((tid & 31) == 0) {
            #pragma unroll
            for (int p = 0; p < 16; p++) redi[(tid >> 5) * 16 + p] = acc[p];
        }
        __syncthreads();
        if (tid < 16) {
            int tot = 0;
            #pragma unroll
            for (int w = 0; w < 8; w++) tot += redi[w * 16 + tid];
            float a = (float)tot * (cmax / QBF) * g_wscale[2 * m];
            float h = 0.5f * a * (1.0f + erff(a * 0.70710678118654752f));
            float ss = h * h;
            #pragma unroll
            for (int o = 8; o > 0; o >>= 1) ss += __shfl_xor_sync(0x0000ffffu, ss, o, 16);
            float nrm = fmaxf(sqrtf(ss), 1e-12f);
            h = h / nrm * 4.0f;
            float am = fabsf(h);
            #pragma unroll
            for (int o = 8; o > 0; o >>= 1) am = fmaxf(am, __shfl_xor_sync(0x0000ffffu, am, o, 16));
            am = fmaxf(am, EPSQ);
            float sa = QBF / am;
            float q = fminf(fmaxf(rintf(h * sa), -128.f), 127.f);
            ((char*)&aqp[0])[tid] = (char)(int)q;
            if (tid == 0) {
                float f = (am / QBF) * g_wscale[2 * m + 1];
                if (m == 0) f *= 0.08838834764831845f;   // fold 1/sqrt(hd) into q
                fct = f;
            }
        }
        __syncthreads();
    }

    // phase B: second bitlinear, bf16 output [bh][s][hd]
    const int a0 = aqp[0], a1 = aqp[1], a2 = aqp[2], a3 = aqp[3];
    const float f = fct;
    #pragma unroll
    for (int j = 0; j < 8; j++) {
        int d = tid + 256 * j;
        int h = d >> 7, dh = d & 127;
        size_t oidx = ((size_t)(b * HEADS + h) * S_LEN + s) * HD + dh;
        const int4 wv = g_wq[2 * m + 1][d];
        int acc = __dp4a(a0, wv.x, 0);
        acc = __dp4a(a1, wv.y, acc);
        acc = __dp4a(a2, wv.z, acc);
        acc = __dp4a(a3, wv.w, acc);
        g_proj[m][oidx] = __float2bfloat16((float)acc * f);
    }
}

// ---------------- V transpose: [bh][s][hd] -> [bh][hd][s] (bf16) ----------------
__global__ __launch_bounds__(256) void vt_kernel() {
    const int s0 = blockIdx.x * 64;
    const int bh = blockIdx.y;
    __shared__ uint32_t tile[64 * 65];

    const uint32_t* src = (const uint32_t*)g_proj[2] + ((size_t)bh * S_LEN + s0) * (HD / 2);
    for (int i = threadIdx.x; i < 64 * 64; i += 256) {
        int r = i >> 6, c = i & 63;
        tile[r * 65 + c] = src[(size_t)r * 64 + c];
    }
    __syncthreads();

    uint32_t* dst = (uint32_t*)g_vt + (size_t)bh * HD * (S_LEN / 2) + (s0 >> 1);
    for (int i = threadIdx.x; i < 64 * 64; i += 256) {
        int kp = i & 31, h2 = i >> 5;             // h2 = hd row 0..127
        uint32_t w0 = tile[(2 * kp) * 65 + (h2 >> 1)];
        uint32_t w1 = tile[(2 * kp + 1) * 65 + (h2 >> 1)];
        uint32_t wo = (h2 & 1) ? __byte_perm(w0, w1, 0x7632) : __byte_perm(w0, w1, 0x5410);
        dst[(size_t)h2 * (S_LEN / 2) + kp] = wo;
    }
}

// ---------------- flash attention: bf16 mma, cp.async double buffer ----------------
#define BM 128
#define BN 64
#define KLD2 68                    // 32-bit words per K/Q row (64 data + 4 pad)
#define VLD2 36                    // words per Vt row (32 data + 4 pad)
#define KBYTES (64 * KLD2 * 4)     // 17408
#define VBYTES (128 * VLD2 * 4)    // 18432
#define BUFB   (KBYTES + VBYTES)   // 35840
#define ATTN_SMEM_BYTES (2 * BUFB) // 71680

__device__ __forceinline__ void mma_bf16(float* d, const uint32_t* a, const uint32_t* b) {
    asm volatile("mma.sync.aligned.m16n8k16.row.col.f32.bf16.bf16.f32 "
        "{%0,%1,%2,%3}, {%4,%5,%6,%7}, {%8,%9}, {%0,%1,%2,%3};"
        : "+f"(d[0]), "+f"(d[1]), "+f"(d[2]), "+f"(d[3])
        : "r"(a[0]), "r"(a[1]), "r"(a[2]), "r"(a[3]), "r"(b[0]), "r"(b[1]));
}

__device__ __forceinline__ uint32_t packbf(float hi, float lo) {
    uint32_t d;
    asm("cvt.rn.bf16x2.f32 %0, %1, %2;" : "=r"(d) : "f"(hi), "f"(lo));
    return d;
}

__device__ __forceinline__ void cpa16(uint32_t dst, const void* src) {
    asm volatile("cp.async.cg.shared.global [%0], [%1], 16;" :: "r"(dst), "l"(src));
}
__device__ __forceinline__ void cpa_commit() {
    asm volatile("cp.async.commit_group;" ::: "memory");
}
template<int N> __device__ __forceinline__ void cpa_wait() {
    asm volatile("cp.async.wait_group %0;" :: "n"(N) : "memory");
}

__global__ __launch_bounds__(256, 1) void attn_kernel(float* __restrict__ out) {
    extern __shared__ char sm[];
    const int bh = blockIdx.y;
    const int q0 = blockIdx.x * BM;
    const int tid = threadIdx.x;
    const int w = tid >> 5;
    const int lane = tid & 31;
    const int g = lane >> 2;
    const int t = lane & 3;

    const uint32_t smb = (uint32_t)__cvta_generic_to_shared(sm);

    // -------- stage Q (already scaled, bf16) --------
    const __nv_bfloat16* qb = g_proj[0] + ((size_t)bh * S_LEN + q0) * HD;
    {
        uint4* smq = (uint4*)sm;
        for (int i = tid; i < 128 * 16; i += 256) {
            int r = i >> 4, c = i & 15;
            smq[r * (KLD2 / 4) + c] = ((const uint4*)(qb + (size_t)r * HD))[c];
        }
    }
    __syncthreads();

    uint32_t qa[8][4];
    {
        const uint32_t* Q = (const uint32_t*)sm;
        const int r0 = (16 * w + g) * KLD2;
        const int r1 = r0 + 8 * KLD2;
        #pragma unroll
        for (int kk = 0; kk < 8; kk++) {
            int c = kk * 8 + t;
            qa[kk][0] = Q[r0 + c];
            qa[kk][1] = Q[r1 + c];
            qa[kk][2] = Q[r0 + c + 4];
            qa[kk][3] = Q[r1 + c + 4];
        }
    }
    __syncthreads();

    const __nv_bfloat16* kbase = g_proj[1] + (size_t)bh * S_LEN * HD;
    const __nv_bfloat16* vtbase = g_vt + (size_t)bh * HD * S_LEN;

    // tile copy via cp.async
    auto copy_tile = [&](int jt, int buf) {
        const __nv_bfloat16* kb = kbase + (size_t)jt * 64 * HD;
        uint32_t kdst = smb + buf * BUFB;
        #pragma unroll
        for (int u = 0; u < 4; u++) {
            int i = tid + u * 256;
            int r = i >> 4, c = i & 15;
            cpa16(kdst + r * (KLD2 * 4) + c * 16, kb + r * HD + c * 8);
        }
        const __nv_bfloat16* vb = vtbase + jt * 64;
        uint32_t vdst = kdst + KBYTES;
        #pragma unroll
        for (int u = 0; u < 4; u++) {
            int i = tid + u * 256;
            int r = i >> 3, c = i & 7;
            cpa16(vdst + r * (VLD2 * 4) + c * 16, vb + (size_t)r * S_LEN + c * 8);
        }
    };

    copy_tile(0, 0); cpa_commit();
    copy_tile(1, 1); cpa_commit();

    float o[16][4];
    #pragma unroll
    for (int nt = 0; nt < 16; nt++) { o[nt][0] = 0.f; o[nt][1] = 0.f; o[nt][2] = 0.f; o[nt][3] = 0.f; }
    float m0 = -INFINITY, m1 = -INFINITY, l0 = 0.f, l1 = 0.f;

    for (int jt = 0; jt < 32; jt++) {
        cpa_wait<1>();
        __syncthreads();

        const uint32_t* KU = (const uint32_t*)(sm + (jt & 1) * BUFB);
        const uint32_t* VU = (const uint32_t*)(sm + (jt & 1) * BUFB + KBYTES);

        // -------- S = Q K^T --------
        float s[8][4];
        #pragma unroll
        for (int nt = 0; nt < 8; nt++) { s[nt][0] = 0.f; s[nt][1] = 0.f; s[nt][2] = 0.f; s[nt][3] = 0.f; }
        #pragma unroll
        for (int kk = 0; kk < 8; kk++) {
            #pragma unroll
            for (int nt = 0; nt < 8; nt++) {
                uint32_t b[2];
                int idx = (nt * 8 + g) * KLD2 + kk * 8 + t;
                b[0] = KU[idx];
                b[1] = KU[idx + 4];
                mma_bf16(s[nt], qa[kk], b);
            }
        }

        // -------- online softmax --------
        float mt0 = -INFINITY, mt1 = -INFINITY;
        #pragma unroll
        for (int nt = 0; nt < 8; nt++) {
            mt0 = fmaxf(mt0, fmaxf(s[nt][0], s[nt][1]));
            mt1 = fmaxf(mt1, fmaxf(s[nt][2], s[nt][3]));
        }
        mt0 = fmaxf(mt0, __shfl_xor_sync(0xffffffffu, mt0, 1));
        mt0 = fmaxf(mt0, __shfl_xor_sync(0xffffffffu, mt0, 2));
        mt1 = fmaxf(mt1, __shfl_xor_sync(0xffffffffu, mt1, 1));
        mt1 = fmaxf(mt1, __shfl_xor_sync(0xffffffffu, mt1, 2));

        float mn0 = fmaxf(m0, mt0), mn1 = fmaxf(m1, mt1);
        float c0 = __expf(m0 - mn0), c1 = __expf(m1 - mn1);
        m0 = mn0; m1 = mn1;

        float rs0 = 0.f, rs1 = 0.f;
        #pragma unroll
        for (int nt = 0; nt < 8; nt++) {
            s[nt][0] = __expf(s[nt][0] - mn0);
            s[nt][1] = __expf(s[nt][1] - mn0);
            s[nt][2] = __expf(s[nt][2] - mn1);
            s[nt][3] = __expf(s[nt][3] - mn1);
            rs0 += s[nt][0] + s[nt][1];
            rs1 += s[nt][2] + s[nt][3];
        }
        rs0 += __shfl_xor_sync(0xffffffffu, rs0, 1);
        rs0 += __shfl_xor_sync(0xffffffffu, rs0, 2);
        rs1 += __shfl_xor_sync(0xffffffffu, rs1, 1);
        rs1 += __shfl_xor_sync(0xffffffffu, rs1, 2);
        l0 = l0 * c0 + rs0;
        l1 = l1 * c1 + rs1;

        #pragma unroll
        for (int nt = 0; nt < 16; nt++) {
            o[nt][0] *= c0; o[nt][1] *= c0;
            o[nt][2] *= c1; o[nt][3] *= c1;
        }

        // -------- O += P @ V  (C-frag layout == A-frag layout for bf16) --------
        #pragma unroll
        for (int kk2 = 0; kk2 < 4; kk2++) {
            const int n0 = 2 * kk2, n1 = 2 * kk2 + 1;
            uint32_t pa[4];
            pa[0] = packbf(s[n0][1], s[n0][0]);   // row g,   k-lo
            pa[1] = packbf(s[n0][3], s[n0][2]);   // row g+8, k-lo
            pa[2] = packbf(s[n1][1], s[n1][0]);   // row g,   k-hi
            pa[3] = packbf(s[n1][3], s[n1][2]);   // row g+8, k-hi
            #pragma unroll
            for (int nt = 0; nt < 16; nt++) {
                uint32_t b[2];
                int idx = (nt * 8 + g) * VLD2 + kk2 * 8 + t;
                b[0] = VU[idx];
                b[1] = VU[idx + 4];
                mma_bf16(o[nt], pa, b);
            }
        }

        __syncthreads();
        if (jt + 2 < 32) copy_tile(jt + 2, jt & 1);
        cpa_commit();
    }

    // -------- epilogue --------
    const int b_ = bh >> 4, h = bh & 15;
    const int row0 = q0 + 16 * w + g;
    const int row1 = row0 + 8;
    const float inv0 = 1.0f / l0;
    const float inv1 = 1.0f / l1;
    float* op0 = out + ((size_t)(b_ * S_LEN + row0)) * D_DIM + h * HD;
    float* op1 = out + ((size_t)(b_ * S_LEN + row1)) * D_DIM + h * HD;
    #pragma unroll
    for (int nt = 0; nt < 16; nt++) {
        int c = nt * 8 + 2 * t;
        *(float2*)(op0 + c) = make_float2(o[nt][0] * inv0, o[nt][1] * inv0);
        *(float2*)(op1 + c) = make_float2(o[nt][2] * inv1, o[nt][3] * inv1);
    }
}

// ---------------- launch ----------------
extern "C" void kernel_launch(void* const* d_in, const int* in_sizes, int n_in,
                              void* d_out, int out_size) {
    const float* x = (const float*)d_in[0];

    quant_weights_kernel<<<6, 1024>>>((const float*)d_in[1], (const float*)d_in[2],
                                      (const float*)d_in[3], (const float*)d_in[4],
                                      (const float*)d_in[5], (const float*)d_in[6]);

    proj_kernel<<<dim3(NTOK, 3), 256>>>(x);

    vt_kernel<<<dim3(S_LEN / 64, BHTOT), 256>>>();

    cudaFuncSetAttribute(attn_kernel, cudaFuncAttributeMaxDynamicSharedMemorySize, ATTN_SMEM_BYTES);
    attn_kernel<<<dim3(S_LEN / BM, BHTOT), 256, ATTN_SMEM_BYTES>>>((float*)d_out);
}

// round 4
// speedup vs baseline: 6.6227x; 1.0367x over previous
#include <cuda_runtime.h>
#include <cuda_bf16.h>
#include <math.h>
#include <stdint.h>

#define EPSQ 1e-5f
#define QBF  127.0f

#define S_LEN 2048
#define D_DIM 2048
#define P_DIM 16
#define HEADS 16
#define HD    128
#define BATCH 2
#define NTOK  (BATCH * S_LEN)
#define BHTOT (BATCH * HEADS)

// ---------------- scratch ----------------
__device__ __nv_bfloat16 g_proj[3][(size_t)BHTOT * S_LEN * HD];   // q(scaled*log2e/sqrt(hd)),k,v
__device__ __nv_bfloat16 g_vt[(size_t)BHTOT * HD * S_LEN];        // v transposed [bh][hd][s]
__device__ int4  g_wq[6][2048];
__device__ float g_wscale[6];

// ---------------- weight quantization ----------------
__global__ __launch_bounds__(1024) void quant_weights_kernel(
        const float* __restrict__ w0, const float* __restrict__ w1,
        const float* __restrict__ w2, const float* __restrict__ w3,
        const float* __restrict__ w4, const float* __restrict__ w5) {
    const float* ws[6] = {w0, w1, w2, w3, w4, w5};
    const int j = blockIdx.x;
    const float* w = ws[j];
    const int N = P_DIM * D_DIM;
    int tid = threadIdx.x;

    float sum = 0.f;
    for (int i = tid; i < N; i += 1024) sum += fabsf(w[i]);
    #pragma unroll
    for (int o = 16; o > 0; o >>= 1) sum += __shfl_xor_sync(0xffffffffu, sum, o);
    __shared__ float red[32];
    __shared__ float s_invws;
    if ((tid & 31) == 0) red[tid >> 5] = sum;
    __syncthreads();
    if (tid == 0) {
        float t = 0.f;
        for (int k = 0; k < 32; k++) t += red[k];
        float mean = t / (float)N;
        float sc = fmaxf(mean, EPSQ);
        g_wscale[j] = sc;
        s_invws = 1.0f / sc;
    }
    __syncthreads();
    float wsv = s_invws;
    char* out = (char*)g_wq[j];
    for (int i = tid; i < N; i += 1024) {
        float q = rintf(w[i] * wsv);
        q = fminf(fmaxf(q, -1.f), 1.f);
        out[i] = (char)(int)q;
    }
}

// ---------------- fused projection (one block per (token, m)) ----------------
__global__ __launch_bounds__(256) void proj_kernel(const float* __restrict__ x) {
    const int t = blockIdx.x;
    const int m = blockIdx.y;
    const int b = t >> 11;
    const int s = t & 2047;
    const int tid = threadIdx.x;

    __shared__ float xs[D_DIM];
    __shared__ int   xq[D_DIM / 4];
    __shared__ int   redi[8 * 16];
    __shared__ float rmax[8];
    __shared__ float s_cmax;
    __shared__ int   aqp[4];
    __shared__ float fct;

    const float* xr = x + (size_t)t * D_DIM;
    float mx = 0.f;
    for (int i = tid; i < D_DIM / 4; i += 256) {
        float4 v = ((const float4*)xr)[i];
        ((float4*)xs)[i] = v;
        mx = fmaxf(mx, fmaxf(fmaxf(fabsf(v.x), fabsf(v.y)), fmaxf(fabsf(v.z), fabsf(v.w))));
    }
    #pragma unroll
    for (int o = 16; o > 0; o >>= 1) mx = fmaxf(mx, __shfl_xor_sync(0xffffffffu, mx, o));
    if ((tid & 31) == 0) rmax[tid >> 5] = mx;
    __syncthreads();
    if (tid == 0) {
        float mm = rmax[0];
        for (int k = 1; k < 8; k++) mm = fmaxf(mm, rmax[k]);
        s_cmax = fmaxf(mm, EPSQ);
    }
    __syncthreads();
    const float cmax = s_cmax;
    const float sx = QBF / cmax;

    {
        int base = tid * 8;
        #pragma unroll
        for (int g = 0; g < 2; g++) {
            int v = 0;
            #pragma unroll
            for (int u = 0; u < 4; u++) {
                float q = rintf(xs[base + g * 4 + u] * sx);
                q = fminf(fmaxf(q, -128.f), 127.f);
                v |= (((int)q) & 0xFF) << (8 * u);
            }
            xq[tid * 2 + g] = v;
        }
    }
    __syncthreads();

    const int x0 = xq[tid * 2 + 0];
    const int x1 = xq[tid * 2 + 1];

    {
        const int* wmat = (const int*)g_wq[2 * m];
        int acc[16];
        #pragma unroll
        for (int p = 0; p < 16; p++) {
            const int* wp = wmat + p * 512;
            int a = __dp4a(x0, wp[tid * 2 + 0], 0);
            a = __dp4a(x1, wp[tid * 2 + 1], a);
            acc[p] = a;
        }
        #pragma unroll
        for (int p = 0; p < 16; p++) acc[p] = __reduce_add_sync(0xffffffffu, acc[p]);
        if ((tid & 31) == 0) {
            #pragma unroll
            for (int p = 0; p < 16; p++) redi[(tid >> 5) * 16 + p] = acc[p];
        }
        __syncthreads();
        if (tid < 16) {
            int tot = 0;
            #pragma unroll
            for (int w = 0; w < 8; w++) tot += redi[w * 16 + tid];
            float a = (float)tot * (cmax / QBF) * g_wscale[2 * m];
            float h = 0.5f * a * (1.0f + erff(a * 0.70710678118654752f));
            float ss = h * h;
            #pragma unroll
            for (int o = 8; o > 0; o >>= 1) ss += __shfl_xor_sync(0x0000ffffu, ss, o, 16);
            float nrm = fmaxf(sqrtf(ss), 1e-12f);
            h = h / nrm * 4.0f;
            float am = fabsf(h);
            #pragma unroll
            for (int o = 8; o > 0; o >>= 1) am = fmaxf(am, __shfl_xor_sync(0x0000ffffu, am, o, 16));
            am = fmaxf(am, EPSQ);
            float sa = QBF / am;
            float q = fminf(fmaxf(rintf(h * sa), -128.f), 127.f);
            ((char*)&aqp[0])[tid] = (char)(int)q;
            if (tid == 0) {
                float f = (am / QBF) * g_wscale[2 * m + 1];
                if (m == 0) f *= 0.08838834764831845f * 1.4426950408889634f; // 1/sqrt(hd) * log2(e)
                fct = f;
            }
        }
        __syncthreads();
    }

    const int a0 = aqp[0], a1 = aqp[1], a2 = aqp[2], a3 = aqp[3];
    const float f = fct;
    #pragma unroll
    for (int j = 0; j < 8; j++) {
        int d = tid + 256 * j;
        int h = d >> 7, dh = d & 127;
        size_t oidx = ((size_t)(b * HEADS + h) * S_LEN + s) * HD + dh;
        const int4 wv = g_wq[2 * m + 1][d];
        int acc = __dp4a(a0, wv.x, 0);
        acc = __dp4a(a1, wv.y, acc);
        acc = __dp4a(a2, wv.z, acc);
        acc = __dp4a(a3, wv.w, acc);
        g_proj[m][oidx] = __float2bfloat16((float)acc * f);
    }
}

// ---------------- V transpose ----------------
__global__ __launch_bounds__(256) void vt_kernel() {
    const int s0 = blockIdx.x * 64;
    const int bh = blockIdx.y;
    __shared__ uint32_t tile[64 * 65];

    const uint32_t* src = (const uint32_t*)g_proj[2] + ((size_t)bh * S_LEN + s0) * (HD / 2);
    for (int i = threadIdx.x; i < 64 * 64; i += 256) {
        int r = i >> 6, c = i & 63;
        tile[r * 65 + c] = src[(size_t)r * 64 + c];
    }
    __syncthreads();

    uint32_t* dst = (uint32_t*)g_vt + (size_t)bh * HD * (S_LEN / 2) + (s0 >> 1);
    for (int i = threadIdx.x; i < 64 * 64; i += 256) {
        int kp = i & 31, h2 = i >> 5;
        uint32_t w0 = tile[(2 * kp) * 65 + (h2 >> 1)];
        uint32_t w1 = tile[(2 * kp + 1) * 65 + (h2 >> 1)];
        uint32_t wo = (h2 & 1) ? __byte_perm(w0, w1, 0x7632) : __byte_perm(w0, w1, 0x5410);
        dst[(size_t)h2 * (S_LEN / 2) + kp] = wo;
    }
}

// ---------------- flash attention: bf16 mma, 4-stage cp.async, skewed pipeline ----------------
#define BM 128
#define BN 64
#define KLD2 68
#define VLD2 36
#define KBYTES (64 * KLD2 * 4)     // 17408
#define VBYTES (128 * VLD2 * 4)    // 18432
#define BUFB   (KBYTES + VBYTES)   // 35840
#define NSTAGE 4
#define ATTN_SMEM_BYTES (NSTAGE * BUFB)   // 143360

__device__ __forceinline__ void mma_bf16(float* d, const uint32_t* a, const uint32_t* b) {
    asm volatile("mma.sync.aligned.m16n8k16.row.col.f32.bf16.bf16.f32 "
        "{%0,%1,%2,%3}, {%4,%5,%6,%7}, {%8,%9}, {%0,%1,%2,%3};"
        : "+f"(d[0]), "+f"(d[1]), "+f"(d[2]), "+f"(d[3])
        : "r"(a[0]), "r"(a[1]), "r"(a[2]), "r"(a[3]), "r"(b[0]), "r"(b[1]));
}

__device__ __forceinline__ uint32_t packbf(float hi, float lo) {
    uint32_t d;
    asm("cvt.rn.bf16x2.f32 %0, %1, %2;" : "=r"(d) : "f"(hi), "f"(lo));
    return d;
}

__device__ __forceinline__ float ex2(float x) {
    float y;
    asm("ex2.approx.f32 %0, %1;" : "=f"(y) : "f"(x));
    return y;
}

__device__ __forceinline__ void cpa16(uint32_t dst, const void* src) {
    asm volatile("cp.async.cg.shared.global [%0], [%1], 16;" :: "r"(dst), "l"(src));
}
__device__ __forceinline__ void cpa_commit() {
    asm volatile("cp.async.commit_group;" ::: "memory");
}
template<int N> __device__ __forceinline__ void cpa_wait() {
    asm volatile("cp.async.wait_group %0;" :: "n"(N) : "memory");
}

__global__ __launch_bounds__(256, 1) void attn_kernel(float* __restrict__ out) {
    extern __shared__ char sm[];
    const int bh = blockIdx.y;
    const int q0 = blockIdx.x * BM;
    const int tid = threadIdx.x;
    const int w = tid >> 5;
    const int lane = tid & 31;
    const int g = lane >> 2;
    const int t = lane & 3;

    const uint32_t smb = (uint32_t)__cvta_generic_to_shared(sm);

    // -------- stage Q (already scaled) through buf0, pull into A-fragments --------
    const __nv_bfloat16* qb = g_proj[0] + ((size_t)bh * S_LEN + q0) * HD;
    {
        uint4* smq = (uint4*)sm;
        for (int i = tid; i < 128 * 16; i += 256) {
            int r = i >> 4, c = i & 15;
            smq[r * (KLD2 / 4) + c] = ((const uint4*)(qb + (size_t)r * HD))[c];
        }
    }
    __syncthreads();

    uint32_t qa[8][4];
    {
        const uint32_t* Q = (const uint32_t*)sm;
        const int r0 = (16 * w + g) * KLD2;
        const int r1 = r0 + 8 * KLD2;
        #pragma unroll
        for (int kk = 0; kk < 8; kk++) {
            int c = kk * 8 + t;
            qa[kk][0] = Q[r0 + c];
            qa[kk][1] = Q[r1 + c];
            qa[kk][2] = Q[r0 + c + 4];
            qa[kk][3] = Q[r1 + c + 4];
        }
    }
    __syncthreads();

    const __nv_bfloat16* kbase = g_proj[1] + (size_t)bh * S_LEN * HD;
    const __nv_bfloat16* vtbase = g_vt + (size_t)bh * HD * S_LEN;

    auto copy_tile = [&](int jt, int buf) {
        const __nv_bfloat16* kb = kbase + (size_t)jt * 64 * HD;
        uint32_t kdst = smb + buf * BUFB;
        #pragma unroll
        for (int u = 0; u < 4; u++) {
            int i = tid + u * 256;
            int r = i >> 4, c = i & 15;
            cpa16(kdst + r * (KLD2 * 4) + c * 16, kb + r * HD + c * 8);
        }
        const __nv_bfloat16* vb = vtbase + jt * 64;
        uint32_t vdst = kdst + KBYTES;
        #pragma unroll
        for (int u = 0; u < 4; u++) {
            int i = tid + u * 256;
            int r = i >> 3, c = i & 7;
            cpa16(vdst + r * (VLD2 * 4) + c * 16, vb + (size_t)r * S_LEN + c * 8);
        }
    };

    copy_tile(0, 0); cpa_commit();
    copy_tile(1, 1); cpa_commit();
    copy_tile(2, 2); cpa_commit();

    float o[16][4];
    #pragma unroll
    for (int nt = 0; nt < 16; nt++) { o[nt][0] = 0.f; o[nt][1] = 0.f; o[nt][2] = 0.f; o[nt][3] = 0.f; }
    float m0 = -INFINITY, m1 = -INFINITY, l0 = 0.f, l1 = 0.f;

    float sA[8][4], sB[8][4];

    // prologue: S_0 into sA
    cpa_wait<2>();
    __syncthreads();
    {
        const uint32_t* KU = (const uint32_t*)sm;   // buf 0
        #pragma unroll
        for (int nt = 0; nt < 8; nt++) { sA[nt][0] = 0.f; sA[nt][1] = 0.f; sA[nt][2] = 0.f; sA[nt][3] = 0.f; }
        #pragma unroll
        for (int kk = 0; kk < 8; kk++) {
            #pragma unroll
            for (int nt = 0; nt < 8; nt++) {
                uint32_t b[2];
                int idx = (nt * 8 + g) * KLD2 + kk * 8 + t;
                b[0] = KU[idx];
                b[1] = KU[idx + 4];
                mma_bf16(sA[nt], qa[kk], b);
            }
        }
    }

    // loop body macro: softmax+PV on SCUR (tile JT), issue S-mma for tile JT+1 into SNXT
    #define ITER_BODY(SCUR, SNXT, JT)                                                     \
    {                                                                                     \
        const int jt_ = (JT);                                                             \
        if (jt_ + 3 < 32) copy_tile(jt_ + 3, (jt_ + 3) & 3);                              \
        cpa_commit();                                                                     \
        cpa_wait<2>();                                                                    \
        __syncthreads();                                                                  \
        if (jt_ < 31) {                                                                   \
            const uint32_t* KU = (const uint32_t*)(sm + ((jt_ + 1) & 3) * BUFB);          \
            _Pragma("unroll")                                                             \
            for (int nt = 0; nt < 8; nt++) {                                              \
                SNXT[nt][0] = 0.f; SNXT[nt][1] = 0.f; SNXT[nt][2] = 0.f; SNXT[nt][3] = 0.f;\
            }                                                                             \
            _Pragma("unroll")                                                             \
            for (int kk = 0; kk < 8; kk++) {                                              \
                _Pragma("unroll")                                                         \
                for (int nt = 0; nt < 8; nt++) {                                          \
                    uint32_t b[2];                                                        \
                    int idx = (nt * 8 + g) * KLD2 + kk * 8 + t;                           \
                    b[0] = KU[idx];                                                       \
                    b[1] = KU[idx + 4];                                                   \
                    mma_bf16(SNXT[nt], qa[kk], b);                                        \
                }                                                                         \
            }                                                                             \
        }                                                                                 \
        float mt0 = -INFINITY, mt1 = -INFINITY;                                           \
        _Pragma("unroll")                                                                 \
        for (int nt = 0; nt < 8; nt++) {                                                  \
            mt0 = fmaxf(mt0, fmaxf(SCUR[nt][0], SCUR[nt][1]));                            \
            mt1 = fmaxf(mt1, fmaxf(SCUR[nt][2], SCUR[nt][3]));                            \
        }                                                                                 \
        mt0 = fmaxf(mt0, __shfl_xor_sync(0xffffffffu, mt0, 1));                           \
        mt0 = fmaxf(mt0, __shfl_xor_sync(0xffffffffu, mt0, 2));                           \
        mt1 = fmaxf(mt1, __shfl_xor_sync(0xffffffffu, mt1, 1));                           \
        mt1 = fmaxf(mt1, __shfl_xor_sync(0xffffffffu, mt1, 2));                           \
        float mn0 = fmaxf(m0, mt0), mn1 = fmaxf(m1, mt1);                                 \
        float c0 = ex2(m0 - mn0), c1 = ex2(m1 - mn1);                                     \
        m0 = mn0; m1 = mn1;                                                               \
        float rs0 = 0.f, rs1 = 0.f;                                                       \
        _Pragma("unroll")                                                                 \
        for (int nt = 0; nt < 8; nt++) {                                                  \
            SCUR[nt][0] = ex2(SCUR[nt][0] - mn0);                                         \
            SCUR[nt][1] = ex2(SCUR[nt][1] - mn0);                                         \
            SCUR[nt][2] = ex2(SCUR[nt][2] - mn1);                                         \
            SCUR[nt][3] = ex2(SCUR[nt][3] - mn1);                                         \
            rs0 += SCUR[nt][0] + SCUR[nt][1];                                             \
            rs1 += SCUR[nt][2] + SCUR[nt][3];                                             \
        }                                                                                 \
        rs0 += __shfl_xor_sync(0xffffffffu, rs0, 1);                                      \
        rs0 += __shfl_xor_sync(0xffffffffu, rs0, 2);                                      \
        rs1 += __shfl_xor_sync(0xffffffffu, rs1, 1);                                      \
        rs1 += __shfl_xor_sync(0xffffffffu, rs1, 2);                                      \
        l0 = l0 * c0 + rs0;                                                               \
        l1 = l1 * c1 + rs1;                                                               \
        _Pragma("unroll")                                                                 \
        for (int nt = 0; nt < 16; nt++) {                                                 \
            o[nt][0] *= c0; o[nt][1] *= c0;                                               \
            o[nt][2] *= c1; o[nt][3] *= c1;                                               \
        }                                                                                 \
        const uint32_t* VU = (const uint32_t*)(sm + (jt_ & 3) * BUFB + KBYTES);           \
        _Pragma("unroll")                                                                 \
        for (int kk2 = 0; kk2 < 4; kk2++) {                                               \
            const int n0 = 2 * kk2, n1 = 2 * kk2 + 1;                                     \
            uint32_t pa[4];                                                               \
            pa[0] = packbf(SCUR[n0][1], SCUR[n0][0]);                                     \
            pa[1] = packbf(SCUR[n0][3], SCUR[n0][2]);                                     \
            pa[2] = packbf(SCUR[n1][1], SCUR[n1][0]);                                     \
            pa[3] = packbf(SCUR[n1][3], SCUR[n1][2]);                                     \
            _Pragma("unroll")                                                             \
            for (int nt = 0; nt < 16; nt++) {                                             \
                uint32_t b[2];                                                            \
                int idx = (nt * 8 + g) * VLD2 + kk2 * 8 + t;                              \
                b[0] = VU[idx];                                                           \
                b[1] = VU[idx + 4];                                                       \
                mma_bf16(o[nt], pa, b);                                                   \
            }                                                                             \
        }                                                                                 \
    }

    #pragma unroll 1
    for (int jt = 0; jt < 32; jt += 2) {
        ITER_BODY(sA, sB, jt);
        ITER_BODY(sB, sA, jt + 1);
    }
    #undef ITER_BODY

    // -------- epilogue --------
    const int b_ = bh >> 4, h = bh & 15;
    const int row0 = q0 + 16 * w + g;
    const int row1 = row0 + 8;
    const float inv0 = 1.0f / l0;
    const float inv1 = 1.0f / l1;
    float* op0 = out + ((size_t)(b_ * S_LEN + row0)) * D_DIM + h * HD;
    float* op1 = out + ((size_t)(b_ * S_LEN + row1)) * D_DIM + h * HD;
    #pragma unroll
    for (int nt = 0; nt < 16; nt++) {
        int c = nt * 8 + 2 * t;
        *(float2*)(op0 + c) = make_float2(o[nt][0] * inv0, o[nt][1] * inv0);
        *(float2*)(op1 + c) = make_float2(o[nt][2] * inv1, o[nt][3] * inv1);
    }
}

// ---------------- launch ----------------
extern "C" void kernel_launch(void* const* d_in, const int* in_sizes, int n_in,
                              void* d_out, int out_size) {
    const float* x = (const float*)d_in[0];

    quant_weights_kernel<<<6, 1024>>>((const float*)d_in[1], (const float*)d_in[2],
                                      (const float*)d_in[3], (const float*)d_in[4],
                                      (const float*)d_in[5], (const float*)d_in[6]);

    proj_kernel<<<dim3(NTOK, 3), 256>>>(x);

    vt_kernel<<<dim3(S_LEN / 64, BHTOT), 256>>>();

    cudaFuncSetAttribute(attn_kernel, cudaFuncAttributeMaxDynamicSharedMemorySize, ATTN_SMEM_BYTES);
    attn_kernel<<<dim3(S_LEN / BM, BHTOT), 256, ATTN_SMEM_BYTES>>>((float*)d_out);
}

// round 5
// speedup vs baseline: 6.9037x; 1.0424x over previous
#include <cuda_runtime.h>
#include <cuda_bf16.h>
#include <math.h>
#include <stdint.h>

#define EPSQ 1e-5f
#define QBF  127.0f

#define S_LEN 2048
#define D_DIM 2048
#define P_DIM 16
#define HEADS 16
#define HD    128
#define BATCH 2
#define NTOK  (BATCH * S_LEN)
#define BHTOT (BATCH * HEADS)

// ---------------- scratch ----------------
__device__ __nv_bfloat16 g_proj[3][(size_t)BHTOT * S_LEN * HD];   // q(scaled*log2e/sqrt(hd)),k,v
__device__ __nv_bfloat16 g_vt[(size_t)BHTOT * HD * S_LEN];        // v transposed [bh][hd][s]
__device__ int4  g_wq[6][2048];
__device__ float g_wscale[6];
__device__ float g_winv[6];

// ---------------- weight scale (reduce only) ----------------
__global__ __launch_bounds__(1024) void quant_scale_kernel(
        const float* __restrict__ w0, const float* __restrict__ w1,
        const float* __restrict__ w2, const float* __restrict__ w3,
        const float* __restrict__ w4, const float* __restrict__ w5) {
    const float* ws[6] = {w0, w1, w2, w3, w4, w5};
    const int j = blockIdx.x;
    const float* w = ws[j];
    const int N = P_DIM * D_DIM;
    int tid = threadIdx.x;

    float sum = 0.f;
    for (int i = tid; i < N; i += 1024) sum += fabsf(w[i]);
    #pragma unroll
    for (int o = 16; o > 0; o >>= 1) sum += __shfl_xor_sync(0xffffffffu, sum, o);
    __shared__ float red[32];
    if ((tid & 31) == 0) red[tid >> 5] = sum;
    __syncthreads();
    if (tid == 0) {
        float t = 0.f;
        for (int k = 0; k < 32; k++) t += red[k];
        float sc = fmaxf(t / (float)N, EPSQ);
        g_wscale[j] = sc;
        g_winv[j] = 1.0f / sc;
    }
}

// ---------------- weight quantize (wide grid) ----------------
__global__ __launch_bounds__(256) void quant_pack_kernel(
        const float* __restrict__ w0, const float* __restrict__ w1,
        const float* __restrict__ w2, const float* __restrict__ w3,
        const float* __restrict__ w4, const float* __restrict__ w5) {
    const float* ws[6] = {w0, w1, w2, w3, w4, w5};
    const int j = blockIdx.y;
    const float* w = ws[j] + blockIdx.x * 4096;
    char* out = (char*)g_wq[j] + blockIdx.x * 4096;
    const float wsv = g_winv[j];
    int tid = threadIdx.x;
    #pragma unroll
    for (int u = 0; u < 4; u++) {
        int i = tid + u * 256 * 4;
        float4 v = ((const float4*)w)[i / 4 + 0];
        // handle 4 consecutive floats per thread via float4
        (void)v;
    }
    // simpler: 16 elems per thread, float4 loads
    #pragma unroll
    for (int u = 0; u < 4; u++) {
        int base = (tid + u * 256) * 4;
        float4 v = *(const float4*)(w + base);
        char4 q;
        float a;
        a = fminf(fmaxf(rintf(v.x * wsv), -1.f), 1.f); q.x = (char)(int)a;
        a = fminf(fmaxf(rintf(v.y * wsv), -1.f), 1.f); q.y = (char)(int)a;
        a = fminf(fmaxf(rintf(v.z * wsv), -1.f), 1.f); q.z = (char)(int)a;
        a = fminf(fmaxf(rintf(v.w * wsv), -1.f), 1.f); q.w = (char)(int)a;
        *(char4*)(out + base) = q;
    }
}

// ---------------- fused projection (one block per (token, m)) ----------------
__global__ __launch_bounds__(256) void proj_kernel(const float* __restrict__ x) {
    const int t = blockIdx.x;
    const int m = blockIdx.y;
    const int b = t >> 11;
    const int s = t & 2047;
    const int tid = threadIdx.x;

    __shared__ float xs[D_DIM];
    __shared__ int   xq[D_DIM / 4];
    __shared__ int   redi[8 * 16];
    __shared__ float rmax[8];
    __shared__ float s_cmax;
    __shared__ int   aqp[4];
    __shared__ float fct;

    const float* xr = x + (size_t)t * D_DIM;
    float mx = 0.f;
    for (int i = tid; i < D_DIM / 4; i += 256) {
        float4 v = ((const float4*)xr)[i];
        ((float4*)xs)[i] = v;
        mx = fmaxf(mx, fmaxf(fmaxf(fabsf(v.x), fabsf(v.y)), fmaxf(fabsf(v.z), fabsf(v.w))));
    }
    #pragma unroll
    for (int o = 16; o > 0; o >>= 1) mx = fmaxf(mx, __shfl_xor_sync(0xffffffffu, mx, o));
    if ((tid & 31) == 0) rmax[tid >> 5] = mx;
    __syncthreads();
    if (tid == 0) {
        float mm = rmax[0];
        for (int k = 1; k < 8; k++) mm = fmaxf(mm, rmax[k]);
        s_cmax = fmaxf(mm, EPSQ);
    }
    __syncthreads();
    const float cmax = s_cmax;
    const float sx = QBF / cmax;

    {
        int base = tid * 8;
        #pragma unroll
        for (int g = 0; g < 2; g++) {
            int v = 0;
            #pragma unroll
            for (int u = 0; u < 4; u++) {
                float q = rintf(xs[base + g * 4 + u] * sx);
                q = fminf(fmaxf(q, -128.f), 127.f);
                v |= (((int)q) & 0xFF) << (8 * u);
            }
            xq[tid * 2 + g] = v;
        }
    }
    __syncthreads();

    const int x0 = xq[tid * 2 + 0];
    const int x1 = xq[tid * 2 + 1];

    {
        const int* wmat = (const int*)g_wq[2 * m];
        int acc[16];
        #pragma unroll
        for (int p = 0; p < 16; p++) {
            const int* wp = wmat + p * 512;
            int a = __dp4a(x0, wp[tid * 2 + 0], 0);
            a = __dp4a(x1, wp[tid * 2 + 1], a);
            acc[p] = a;
        }
        #pragma unroll
        for (int p = 0; p < 16; p++) acc[p] = __reduce_add_sync(0xffffffffu, acc[p]);
        if ((tid & 31) == 0) {
            #pragma unroll
            for (int p = 0; p < 16; p++) redi[(tid >> 5) * 16 + p] = acc[p];
        }
        __syncthreads();
        if (tid < 16) {
            int tot = 0;
            #pragma unroll
            for (int w = 0; w < 8; w++) tot += redi[w * 16 + tid];
            float a = (float)tot * (cmax / QBF) * g_wscale[2 * m];
            float h = 0.5f * a * (1.0f + erff(a * 0.70710678118654752f));
            float ss = h * h;
            #pragma unroll
            for (int o = 8; o > 0; o >>= 1) ss += __shfl_xor_sync(0x0000ffffu, ss, o, 16);
            float nrm = fmaxf(sqrtf(ss), 1e-12f);
            h = h / nrm * 4.0f;
            float am = fabsf(h);
            #pragma unroll
            for (int o = 8; o > 0; o >>= 1) am = fmaxf(am, __shfl_xor_sync(0x0000ffffu, am, o, 16));
            am = fmaxf(am, EPSQ);
            float sa = QBF / am;
            float q = fminf(fmaxf(rintf(h * sa), -128.f), 127.f);
            ((char*)&aqp[0])[tid] = (char)(int)q;
            if (tid == 0) {
                float f = (am / QBF) * g_wscale[2 * m + 1];
                if (m == 0) f *= 0.08838834764831845f * 1.4426950408889634f; // 1/sqrt(hd) * log2(e)
                fct = f;
            }
        }
        __syncthreads();
    }

    const int a0 = aqp[0], a1 = aqp[1], a2 = aqp[2], a3 = aqp[3];
    const float f = fct;
    #pragma unroll
    for (int j = 0; j < 8; j++) {
        int d = tid + 256 * j;
        int h = d >> 7, dh = d & 127;
        size_t oidx = ((size_t)(b * HEADS + h) * S_LEN + s) * HD + dh;
        const int4 wv = g_wq[2 * m + 1][d];
        int acc = __dp4a(a0, wv.x, 0);
        acc = __dp4a(a1, wv.y, acc);
        acc = __dp4a(a2, wv.z, acc);
        acc = __dp4a(a3, wv.w, acc);
        g_proj[m][oidx] = __float2bfloat16((float)acc * f);
    }
}

// ---------------- V transpose ----------------
__global__ __launch_bounds__(256) void vt_kernel() {
    const int s0 = blockIdx.x * 64;
    const int bh = blockIdx.y;
    __shared__ uint32_t tile[64 * 65];

    const uint32_t* src = (const uint32_t*)g_proj[2] + ((size_t)bh * S_LEN + s0) * (HD / 2);
    for (int i = threadIdx.x; i < 64 * 64; i += 256) {
        int r = i >> 6, c = i & 63;
        tile[r * 65 + c] = src[(size_t)r * 64 + c];
    }
    __syncthreads();

    uint32_t* dst = (uint32_t*)g_vt + (size_t)bh * HD * (S_LEN / 2) + (s0 >> 1);
    for (int i = threadIdx.x; i < 64 * 64; i += 256) {
        int kp = i & 31, h2 = i >> 5;
        uint32_t w0 = tile[(2 * kp) * 65 + (h2 >> 1)];
        uint32_t w1 = tile[(2 * kp + 1) * 65 + (h2 >> 1)];
        uint32_t wo = (h2 & 1) ? __byte_perm(w0, w1, 0x7632) : __byte_perm(w0, w1, 0x5410);
        dst[(size_t)h2 * (S_LEN / 2) + kp] = wo;
    }
}

// ---------------- flash attention: bf16 mma + ldmatrix, 4-stage cp.async ----------------
#define BM 128
#define BN 64
#define KLD2 68
#define VLD2 36
#define KBYTES (64 * KLD2 * 4)     // 17408
#define VBYTES (128 * VLD2 * 4)    // 18432
#define BUFB   (KBYTES + VBYTES)   // 35840
#define NSTAGE 4
#define ATTN_SMEM_BYTES (NSTAGE * BUFB)   // 143360

__device__ __forceinline__ void mma_bf16(float* d, const uint32_t* a, const uint32_t b0, const uint32_t b1) {
    asm volatile("mma.sync.aligned.m16n8k16.row.col.f32.bf16.bf16.f32 "
        "{%0,%1,%2,%3}, {%4,%5,%6,%7}, {%8,%9}, {%0,%1,%2,%3};"
        : "+f"(d[0]), "+f"(d[1]), "+f"(d[2]), "+f"(d[3])
        : "r"(a[0]), "r"(a[1]), "r"(a[2]), "r"(a[3]), "r"(b0), "r"(b1));
}

__device__ __forceinline__ void ldsm4(uint32_t& r0, uint32_t& r1, uint32_t& r2, uint32_t& r3, uint32_t addr) {
    asm volatile("ldmatrix.sync.aligned.m8n8.x4.shared.b16 {%0,%1,%2,%3}, [%4];"
        : "=r"(r0), "=r"(r1), "=r"(r2), "=r"(r3) : "r"(addr));
}

__device__ __forceinline__ uint32_t packbf(float hi, float lo) {
    uint32_t d;
    asm("cvt.rn.bf16x2.f32 %0, %1, %2;" : "=r"(d) : "f"(hi), "f"(lo));
    return d;
}

__device__ __forceinline__ float ex2(float x) {
    float y;
    asm("ex2.approx.f32 %0, %1;" : "=f"(y) : "f"(x));
    return y;
}

__device__ __forceinline__ void cpa16(uint32_t dst, const void* src) {
    asm volatile("cp.async.cg.shared.global [%0], [%1], 16;" :: "r"(dst), "l"(src));
}
__device__ __forceinline__ void cpa_commit() {
    asm volatile("cp.async.commit_group;" ::: "memory");
}
template<int N> __device__ __forceinline__ void cpa_wait() {
    asm volatile("cp.async.wait_group %0;" :: "n"(N) : "memory");
}

__global__ __launch_bounds__(256, 1) void attn_kernel(float* __restrict__ out) {
    extern __shared__ char sm[];
    const int bh = blockIdx.y;
    const int q0 = blockIdx.x * BM;
    const int tid = threadIdx.x;
    const int w = tid >> 5;
    const int lane = tid & 31;
    const int g = lane >> 2;
    const int t = lane & 3;

    const uint32_t smb = (uint32_t)__cvta_generic_to_shared(sm);

    // per-thread ldmatrix base byte-offsets
    const int lr = lane & 7;
    const int kh = (lane >> 3) & 1;   // +8 k elements (4 words)
    const int nh = (lane >> 4) & 1;   // +8 rows
    uint32_t koff[4];
    #pragma unroll
    for (int ntp = 0; ntp < 4; ntp++)
        koff[ntp] = ((16 * ntp + 8 * nh + lr) * KLD2 + kh * 4) * 4;
    uint32_t voff[8];
    #pragma unroll
    for (int ntp = 0; ntp < 8; ntp++)
        voff[ntp] = ((16 * ntp + 8 * nh + lr) * VLD2 + kh * 4) * 4 + KBYTES;

    // -------- stage Q (already scaled) through buf0, pull into A-fragments --------
    const __nv_bfloat16* qb = g_proj[0] + ((size_t)bh * S_LEN + q0) * HD;
    {
        uint4* smq = (uint4*)sm;
        for (int i = tid; i < 128 * 16; i += 256) {
            int r = i >> 4, c = i & 15;
            smq[r * (KLD2 / 4) + c] = ((const uint4*)(qb + (size_t)r * HD))[c];
        }
    }
    __syncthreads();

    uint32_t qa[8][4];
    {
        const uint32_t* Q = (const uint32_t*)sm;
        const int r0 = (16 * w + g) * KLD2;
        const int r1 = r0 + 8 * KLD2;
        #pragma unroll
        for (int kk = 0; kk < 8; kk++) {
            int c = kk * 8 + t;
            qa[kk][0] = Q[r0 + c];
            qa[kk][1] = Q[r1 + c];
            qa[kk][2] = Q[r0 + c + 4];
            qa[kk][3] = Q[r1 + c + 4];
        }
    }
    __syncthreads();

    const __nv_bfloat16* kbase = g_proj[1] + (size_t)bh * S_LEN * HD;
    const __nv_bfloat16* vtbase = g_vt + (size_t)bh * HD * S_LEN;

    auto copy_tile = [&](int jt, int buf) {
        const __nv_bfloat16* kb = kbase + (size_t)jt * 64 * HD;
        uint32_t kdst = smb + buf * BUFB;
        #pragma unroll
        for (int u = 0; u < 4; u++) {
            int i = tid + u * 256;
            int r = i >> 4, c = i & 15;
            cpa16(kdst + r * (KLD2 * 4) + c * 16, kb + r * HD + c * 8);
        }
        const __nv_bfloat16* vb = vtbase + jt * 64;
        uint32_t vdst = kdst + KBYTES;
        #pragma unroll
        for (int u = 0; u < 4; u++) {
            int i = tid + u * 256;
            int r = i >> 3, c = i & 7;
            cpa16(vdst + r * (VLD2 * 4) + c * 16, vb + (size_t)r * S_LEN + c * 8);
        }
    };

    copy_tile(0, 0); cpa_commit();
    copy_tile(1, 1); cpa_commit();
    copy_tile(2, 2); cpa_commit();

    float o[16][4];
    #pragma unroll
    for (int nt = 0; nt < 16; nt++) { o[nt][0] = 0.f; o[nt][1] = 0.f; o[nt][2] = 0.f; o[nt][3] = 0.f; }
    float m0 = -INFINITY, m1 = -INFINITY, l0 = 0.f, l1 = 0.f;

    float sA[8][4], sB[8][4];

    // prologue: S_0 into sA
    cpa_wait<2>();
    __syncthreads();
    {
        const uint32_t kb0 = smb;   // buf 0
        #pragma unroll
        for (int nt = 0; nt < 8; nt++) { sA[nt][0] = 0.f; sA[nt][1] = 0.f; sA[nt][2] = 0.f; sA[nt][3] = 0.f; }
        #pragma unroll
        for (int kk = 0; kk < 8; kk++) {
            #pragma unroll
            for (int ntp = 0; ntp < 4; ntp++) {
                uint32_t r0, r1, r2, r3;
                ldsm4(r0, r1, r2, r3, kb0 + koff[ntp] + kk * 32);
                mma_bf16(sA[2 * ntp], qa[kk], r0, r1);
                mma_bf16(sA[2 * ntp + 1], qa[kk], r2, r3);
            }
        }
    }

    #define ITER_BODY(SCUR, SNXT, JT)                                                     \
    {                                                                                     \
        const int jt_ = (JT);                                                             \
        if (jt_ + 3 < 32) copy_tile(jt_ + 3, (jt_ + 3) & 3);                              \
        cpa_commit();                                                                     \
        cpa_wait<2>();                                                                    \
        __syncthreads();                                                                  \
        if (jt_ < 31) {                                                                   \
            const uint32_t kbN = smb + ((jt_ + 1) & 3) * BUFB;                            \
            _Pragma("unroll")                                                             \
            for (int nt = 0; nt < 8; nt++) {                                              \
                SNXT[nt][0] = 0.f; SNXT[nt][1] = 0.f; SNXT[nt][2] = 0.f; SNXT[nt][3] = 0.f;\
            }                                                                             \
            _Pragma("unroll")                                                             \
            for (int kk = 0; kk < 8; kk++) {                                              \
                _Pragma("unroll")                                                         \
                for (int ntp = 0; ntp < 4; ntp++) {                                       \
                    uint32_t r0, r1, r2, r3;                                              \
                    ldsm4(r0, r1, r2, r3, kbN + koff[ntp] + kk * 32);                     \
                    mma_bf16(SNXT[2 * ntp], qa[kk], r0, r1);                              \
                    mma_bf16(SNXT[2 * ntp + 1], qa[kk], r2, r3);                          \
                }                                                                         \
            }                                                                             \
        }                                                                                 \
        float mt0 = -INFINITY, mt1 = -INFINITY;                                           \
        _Pragma("unroll")                                                                 \
        for (int nt = 0; nt < 8; nt++) {                                                  \
            mt0 = fmaxf(mt0, fmaxf(SCUR[nt][0], SCUR[nt][1]));                            \
            mt1 = fmaxf(mt1, fmaxf(SCUR[nt][2], SCUR[nt][3]));                            \
        }                                                                                 \
        mt0 = fmaxf(mt0, __shfl_xor_sync(0xffffffffu, mt0, 1));                           \
        mt0 = fmaxf(mt0, __shfl_xor_sync(0xffffffffu, mt0, 2));                           \
        mt1 = fmaxf(mt1, __shfl_xor_sync(0xffffffffu, mt1, 1));                           \
        mt1 = fmaxf(mt1, __shfl_xor_sync(0xffffffffu, mt1, 2));                           \
        float mn0 = fmaxf(m0, mt0), mn1 = fmaxf(m1, mt1);                                 \
        float c0 = ex2(m0 - mn0), c1 = ex2(m1 - mn1);                                     \
        m0 = mn0; m1 = mn1;                                                               \
        float rs0 = 0.f, rs1 = 0.f;                                                       \
        _Pragma("unroll")                                                                 \
        for (int nt = 0; nt < 8; nt++) {                                                  \
            SCUR[nt][0] = ex2(SCUR[nt][0] - mn0);                                         \
            SCUR[nt][1] = ex2(SCUR[nt][1] - mn0);                                         \
            SCUR[nt][2] = ex2(SCUR[nt][2] - mn1);                                         \
            SCUR[nt][3] = ex2(SCUR[nt][3] - mn1);                                         \
            rs0 += SCUR[nt][0] + SCUR[nt][1];                                             \
            rs1 += SCUR[nt][2] + SCUR[nt][3];                                             \
        }                                                                                 \
        rs0 += __shfl_xor_sync(0xffffffffu, rs0, 1);                                      \
        rs0 += __shfl_xor_sync(0xffffffffu, rs0, 2);                                      \
        rs1 += __shfl_xor_sync(0xffffffffu, rs1, 1);                                      \
        rs1 += __shfl_xor_sync(0xffffffffu, rs1, 2);                                      \
        l0 = l0 * c0 + rs0;                                                               \
        l1 = l1 * c1 + rs1;                                                               \
        _Pragma("unroll")                                                                 \
        for (int nt = 0; nt < 16; nt++) {                                                 \
            o[nt][0] *= c0; o[nt][1] *= c0;                                               \
            o[nt][2] *= c1; o[nt][3] *= c1;                                               \
        }                                                                                 \
        uint32_t pa[4][4];                                                                \
        _Pragma("unroll")                                                                 \
        for (int kk2 = 0; kk2 < 4; kk2++) {                                               \
            const int n0 = 2 * kk2, n1 = 2 * kk2 + 1;                                     \
            pa[kk2][0] = packbf(SCUR[n0][1], SCUR[n0][0]);                                \
            pa[kk2][1] = packbf(SCUR[n0][3], SCUR[n0][2]);                                \
            pa[kk2][2] = packbf(SCUR[n1][1], SCUR[n1][0]);                                \
            pa[kk2][3] = packbf(SCUR[n1][3], SCUR[n1][2]);                                \
        }                                                                                 \
        const uint32_t vbC = smb + (jt_ & 3) * BUFB;                                      \
        _Pragma("unroll")                                                                 \
        for (int kk2 = 0; kk2 < 4; kk2++) {                                               \
            _Pragma("unroll")                                                             \
            for (int ntp = 0; ntp < 8; ntp++) {                                           \
                uint32_t r0, r1, r2, r3;                                                  \
                ldsm4(r0, r1, r2, r3, vbC + voff[ntp] + kk2 * 32);                        \
                mma_bf16(o[2 * ntp], pa[kk2], r0, r1);                                    \
                mma_bf16(o[2 * ntp + 1], pa[kk2], r2, r3);                                \
            }                                                                             \
        }                                                                                 \
    }

    #pragma unroll 1
    for (int jt = 0; jt < 32; jt += 2) {
        ITER_BODY(sA, sB, jt);
        ITER_BODY(sB, sA, jt + 1);
    }
    #undef ITER_BODY

    // -------- epilogue --------
    const int b_ = bh >> 4, h = bh & 15;
    const int row0 = q0 + 16 * w + g;
    const int row1 = row0 + 8;
    const float inv0 = 1.0f / l0;
    const float inv1 = 1.0f / l1;
    float* op0 = out + ((size_t)(b_ * S_LEN + row0)) * D_DIM + h * HD;
    float* op1 = out + ((size_t)(b_ * S_LEN + row1)) * D_DIM + h * HD;
    #pragma unroll
    for (int nt = 0; nt < 16; nt++) {
        int c = nt * 8 + 2 * t;
        *(float2*)(op0 + c) = make_float2(o[nt][0] * inv0, o[nt][1] * inv0);
        *(float2*)(op1 + c) = make_float2(o[nt][2] * inv1, o[nt][3] * inv1);
    }
}

// ---------------- launch ----------------
extern "C" void kernel_launch(void* const* d_in, const int* in_sizes, int n_in,
                              void* d_out, int out_size) {
    const float* x = (const float*)d_in[0];
    const float* w1 = (const float*)d_in[1];
    const float* w2 = (const float*)d_in[2];
    const float* w3 = (const float*)d_in[3];
    const float* w4 = (const float*)d_in[4];
    const float* w5 = (const float*)d_in[5];
    const float* w6 = (const float*)d_in[6];

    quant_scale_kernel<<<6, 1024>>>(w1, w2, w3, w4, w5, w6);
    quant_pack_kernel<<<dim3(8, 6), 256>>>(w1, w2, w3, w4, w5, w6);

    proj_kernel<<<dim3(NTOK, 3), 256>>>(x);

    vt_kernel<<<dim3(S_LEN / 64, BHTOT), 256>>>();

    cudaFuncSetAttribute(attn_kernel, cudaFuncAttributeMaxDynamicSharedMemorySize, ATTN_SMEM_BYTES);
    attn_kernel<<<dim3(S_LEN / BM, BHTOT), 256, ATTN_SMEM_BYTES>>>((float*)d_out);
}